// round 1
// baseline (speedup 1.0000x reference)
#include <cuda_runtime.h>

// Problem constants
#define NTOK   (8 * 2048)     // 16384 tokens
#define EDIM   512
#define NHEAD  64
#define DK     8

// Scratch: attention output already stored in the torch-"bug" permuted layout,
// so the final linear is a plain row-major GEMM over it.
// flat index within batch: h*16384 + s*8 + d  ==  (output row t)*512 + c
__device__ float g_scratch[NTOK * EDIM];

typedef unsigned long long u64;

__device__ __forceinline__ u64 pack2f(float lo, float hi) {
    u64 r;
    asm("mov.b64 %0, {%1, %2};" : "=l"(r) : "f"(lo), "f"(hi));
    return r;
}
__device__ __forceinline__ void fma2(u64 &d, u64 a, u64 b) {
    asm("fma.rn.f32x2 %0, %1, %2, %3;" : "=l"(d) : "l"(a), "l"(b), "l"(d));
}
__device__ __forceinline__ float2 unpack2f(u64 v) {
    float2 r;
    asm("mov.b64 {%0, %1}, %2;" : "=f"(r.x), "=f"(r.y) : "l"(v));
    return r;
}

// ---------------------------------------------------------------------------
// Kernel A: per-token quantum projection + head-axis attention.
// One warp per token; each lane owns heads (lane) and (lane+32).
// Scores bounded: |P_h . P_g| <= 8, /sqrt(8) -> |s| <= 2.83, so softmax
// needs no max subtraction -> single streaming pass, no score array.
// ---------------------------------------------------------------------------
__global__ __launch_bounds__(256) void qattn_kernel(const float* __restrict__ x,
                                                    const float* __restrict__ theta) {
    __shared__ float Psm[8][NHEAD][DK];   // 16 KB: per-warp projection matrix
    __shared__ float th[DK];

    const int tid  = threadIdx.x;
    if (tid < DK) th[tid] = theta[tid];
    __syncthreads();

    const int w    = tid >> 5;
    const int lane = tid & 31;
    const int token = blockIdx.x * 8 + w;
    const float* xr = x + (size_t)token * EDIM;

    // Load the 2 head rows this lane owns and apply cos(x + theta)
    float pa[8], pb[8];
    {
        float4 v0 = *(const float4*)(xr + lane * 8);
        float4 v1 = *(const float4*)(xr + lane * 8 + 4);
        pa[0] = cosf(v0.x + th[0]); pa[1] = cosf(v0.y + th[1]);
        pa[2] = cosf(v0.z + th[2]); pa[3] = cosf(v0.w + th[3]);
        pa[4] = cosf(v1.x + th[4]); pa[5] = cosf(v1.y + th[5]);
        pa[6] = cosf(v1.z + th[6]); pa[7] = cosf(v1.w + th[7]);
        float4 u0 = *(const float4*)(xr + (lane + 32) * 8);
        float4 u1 = *(const float4*)(xr + (lane + 32) * 8 + 4);
        pb[0] = cosf(u0.x + th[0]); pb[1] = cosf(u0.y + th[1]);
        pb[2] = cosf(u0.z + th[2]); pb[3] = cosf(u0.w + th[3]);
        pb[4] = cosf(u1.x + th[4]); pb[5] = cosf(u1.y + th[5]);
        pb[6] = cosf(u1.z + th[6]); pb[7] = cosf(u1.w + th[7]);
    }

    float* Pw = &Psm[w][0][0];
    *(float4*)(Pw + lane * 8)          = make_float4(pa[0], pa[1], pa[2], pa[3]);
    *(float4*)(Pw + lane * 8 + 4)      = make_float4(pa[4], pa[5], pa[6], pa[7]);
    *(float4*)(Pw + (lane + 32) * 8)     = make_float4(pb[0], pb[1], pb[2], pb[3]);
    *(float4*)(Pw + (lane + 32) * 8 + 4) = make_float4(pb[4], pb[5], pb[6], pb[7]);
    __syncwarp();

    // Pre-scale query rows by 1/sqrt(d) so the dot directly yields the score.
    const float inv = 0.35355339059327373f;
    float qa[8], qb[8];
#pragma unroll
    for (int d = 0; d < 8; d++) { qa[d] = pa[d] * inv; qb[d] = pb[d] * inv; }

    float suma = 0.f, sumb = 0.f;
    float oa[8], ob[8];
#pragma unroll
    for (int d = 0; d < 8; d++) { oa[d] = 0.f; ob[d] = 0.f; }

#pragma unroll 8
    for (int g = 0; g < NHEAD; g++) {
        float4 r0 = *(const float4*)(Pw + g * 8);
        float4 r1 = *(const float4*)(Pw + g * 8 + 4);
        float sa = qa[0]*r0.x + qa[1]*r0.y + qa[2]*r0.z + qa[3]*r0.w
                 + qa[4]*r1.x + qa[5]*r1.y + qa[6]*r1.z + qa[7]*r1.w;
        float sb = qb[0]*r0.x + qb[1]*r0.y + qb[2]*r0.z + qb[3]*r0.w
                 + qb[4]*r1.x + qb[5]*r1.y + qb[6]*r1.z + qb[7]*r1.w;
        float wa = __expf(sa);
        float wb = __expf(sb);
        suma += wa; sumb += wb;
        oa[0] += wa*r0.x; oa[1] += wa*r0.y; oa[2] += wa*r0.z; oa[3] += wa*r0.w;
        oa[4] += wa*r1.x; oa[5] += wa*r1.y; oa[6] += wa*r1.z; oa[7] += wa*r1.w;
        ob[0] += wb*r0.x; ob[1] += wb*r0.y; ob[2] += wb*r0.z; ob[3] += wb*r0.w;
        ob[4] += wb*r1.x; ob[5] += wb*r1.y; ob[6] += wb*r1.z; ob[7] += wb*r1.w;
    }

    const float ra = 1.0f / suma;
    const float rb = 1.0f / sumb;
    const int b = token >> 11;        // token / 2048
    const int s = token & 2047;       // token % 2048

    // Permuted store: scratch[b*2^20 + h*2^14 + s*8 + d]
    float* dstA = g_scratch + ((size_t)b << 20) + ((size_t)lane << 14) + s * 8;
    float* dstB = g_scratch + ((size_t)b << 20) + ((size_t)(lane + 32) << 14) + s * 8;
    *(float4*)(dstA)     = make_float4(oa[0]*ra, oa[1]*ra, oa[2]*ra, oa[3]*ra);
    *(float4*)(dstA + 4) = make_float4(oa[4]*ra, oa[5]*ra, oa[6]*ra, oa[7]*ra);
    *(float4*)(dstB)     = make_float4(ob[0]*rb, ob[1]*rb, ob[2]*rb, ob[3]*rb);
    *(float4*)(dstB + 4) = make_float4(ob[4]*rb, ob[5]*rb, ob[6]*rb, ob[7]*rb);
}

// ---------------------------------------------------------------------------
// Kernel B: Y[16384,512] = Z[16384,512] @ W^T + bias, all fp32, via packed
// fp32x2 FFMA (pairs packed along K -> no per-iteration packing instructions).
// 128x128 block tile, 8x8 (x2-k) per thread, stride-16 row/col ownership so
// b-fragment LDS.64 is bank-conflict-free.
// ---------------------------------------------------------------------------
#define BM 128
#define BN 128
#define BK 8
#define KP (BK / 2)

__global__ __launch_bounds__(256) void gemm_kernel(const float* __restrict__ W,
                                                   const float* __restrict__ bias,
                                                   float* __restrict__ Y) {
    __shared__ u64 Zst[KP][BM];   // 4 KB, packed (k, k+1) pairs
    __shared__ u64 Wst[KP][BN];   // 4 KB

    const int tid = threadIdx.x;
    const int bx = blockIdx.x;    // N tile: 0..3
    const int by = blockIdx.y;    // M tile: 0..127

    const int lr  = tid >> 1;          // 0..127: tile row loaded by this thread
    const int lk  = (tid & 1) * 4;     // 0 or 4: k offset
    const int lkp = lk >> 1;           // 0 or 2: k-pair slot

    const float* Zg = g_scratch + (size_t)(by * BM + lr) * EDIM + lk;
    const float* Wg = W        + (size_t)(bx * BN + lr) * EDIM + lk;

    const int tx = tid & 15;   // column group (owns cols tx + 16j)
    const int ty = tid >> 4;   // row group    (owns rows ty + 16i)

    u64 acc[8][8];
#pragma unroll
    for (int i = 0; i < 8; i++)
#pragma unroll
        for (int j = 0; j < 8; j++) acc[i][j] = 0ull;

    float4 zv = *(const float4*)(Zg);
    float4 wv = *(const float4*)(Wg);

    for (int k0 = 0; k0 < EDIM; k0 += BK) {
        __syncthreads();
        Zst[lkp][lr]     = pack2f(zv.x, zv.y);
        Zst[lkp + 1][lr] = pack2f(zv.z, zv.w);
        Wst[lkp][lr]     = pack2f(wv.x, wv.y);
        Wst[lkp + 1][lr] = pack2f(wv.z, wv.w);
        __syncthreads();

        if (k0 + BK < EDIM) {   // prefetch next tile while computing
            zv = *(const float4*)(Zg + k0 + BK);
            wv = *(const float4*)(Wg + k0 + BK);
        }

#pragma unroll
        for (int kp = 0; kp < KP; kp++) {
            u64 a[8], bfr[8];
#pragma unroll
            for (int i = 0; i < 8; i++) a[i]   = Zst[kp][ty + 16 * i];
#pragma unroll
            for (int j = 0; j < 8; j++) bfr[j] = Wst[kp][tx + 16 * j];
#pragma unroll
            for (int i = 0; i < 8; i++)
#pragma unroll
                for (int j = 0; j < 8; j++)
                    fma2(acc[i][j], a[i], bfr[j]);
        }
    }

    // Epilogue: reduce the (even-k, odd-k) partial sums, add bias, store.
    float bc[8];
#pragma unroll
    for (int j = 0; j < 8; j++) bc[j] = bias[bx * BN + tx + 16 * j];

#pragma unroll
    for (int i = 0; i < 8; i++) {
        const int row = by * BM + ty + 16 * i;
        float* yr = Y + (size_t)row * EDIM + bx * BN;
#pragma unroll
        for (int j = 0; j < 8; j++) {
            float2 v = unpack2f(acc[i][j]);
            yr[tx + 16 * j] = v.x + v.y + bc[j];
        }
    }
}

// ---------------------------------------------------------------------------
extern "C" void kernel_launch(void* const* d_in, const int* in_sizes, int n_in,
                              void* d_out, int out_size) {
    const float* x     = (const float*)d_in[0];
    const float* theta = (const float*)d_in[1];
    const float* W     = (const float*)d_in[2];
    const float* bias  = (const float*)d_in[3];
    float* out = (float*)d_out;

    qattn_kernel<<<NTOK / 8, 256>>>(x, theta);
    gemm_kernel<<<dim3(EDIM / BN, NTOK / BM), 256>>>(W, bias, out);
}

// round 3
// speedup vs baseline: 1.6747x; 1.6747x over previous
#include <cuda_runtime.h>
#include <cuda_bf16.h>
#include <cstdint>

#define NTOK   (8 * 2048)
#define EDIM   512
#define NHEAD  64
#define DK     8

// Split-bf16 operands (hi + lo together carry ~17 mantissa bits of fp32)
__device__ __nv_bfloat16 g_Zh[NTOK * EDIM];
__device__ __nv_bfloat16 g_Zl[NTOK * EDIM];
__device__ __nv_bfloat16 g_Wh[EDIM * EDIM];
__device__ __nv_bfloat16 g_Wl[EDIM * EDIM];

__device__ __forceinline__ uint32_t smem_to_u32(const void* p) {
    uint32_t a;
    asm("{ .reg .u64 t; cvta.to.shared.u64 t, %1; cvt.u32.u64 %0, t; }" : "=r"(a) : "l"(p));
    return a;
}

// Baseline-PTX building blocks (sm_80+: cp.async, ldmatrix, bf16 mma.sync)
#define CP16(dst, src) \
    asm volatile("cp.async.cg.shared.global [%0], [%1], 16;" :: "r"(dst), "l"(src))
#define CP_COMMIT()  asm volatile("cp.async.commit_group;" ::: "memory")
#define CP_WAIT1()   asm volatile("cp.async.wait_group 1;" ::: "memory")
#define CP_WAIT0()   asm volatile("cp.async.wait_group 0;" ::: "memory")

#define LDSM4(r, addr) \
    asm volatile("ldmatrix.sync.aligned.m8n8.x4.shared.b16 {%0,%1,%2,%3}, [%4];" \
        : "=r"((r)[0]), "=r"((r)[1]), "=r"((r)[2]), "=r"((r)[3]) : "r"(addr))

#define MMA_BF16(d, a, b) \
    asm volatile("mma.sync.aligned.m16n8k16.row.col.f32.bf16.bf16.f32 " \
        "{%0,%1,%2,%3}, {%4,%5,%6,%7}, {%8,%9}, {%0,%1,%2,%3};" \
        : "+f"((d)[0]), "+f"((d)[1]), "+f"((d)[2]), "+f"((d)[3]) \
        : "r"((a)[0]), "r"((a)[1]), "r"((a)[2]), "r"((a)[3]), "r"((b)[0]), "r"((b)[1]))

// ---------------------------------------------------------------------------
// Split W into bf16 hi/lo
// ---------------------------------------------------------------------------
__global__ void wsplit_kernel(const float* __restrict__ W) {
    int i = blockIdx.x * 256 + threadIdx.x;
    float w = W[i];
    __nv_bfloat16 h = __float2bfloat16(w);
    g_Wh[i] = h;
    g_Wl[i] = __float2bfloat16(w - __bfloat162float(h));
}

// ---------------------------------------------------------------------------
// Kernel A: projection + head-axis attention (one warp / token).
// Bounded scores (|s| <= 2.83) -> streaming softmax without max pass.
// Emits the attention output in the torch-permuted layout as bf16 hi/lo.
// ---------------------------------------------------------------------------
__global__ __launch_bounds__(256) void qattn_kernel(const float* __restrict__ x,
                                                    const float* __restrict__ theta) {
    __shared__ float Psm[8][NHEAD][DK];
    __shared__ float th[DK];
    const int tid = threadIdx.x;
    if (tid < DK) th[tid] = theta[tid];
    __syncthreads();

    const int w = tid >> 5, lane = tid & 31;
    const int token = blockIdx.x * 8 + w;
    const float* xr = x + (size_t)token * EDIM;

    float pa[8], pb[8];
    {
        float4 v0 = *(const float4*)(xr + lane * 8);
        float4 v1 = *(const float4*)(xr + lane * 8 + 4);
        pa[0] = __cosf(v0.x + th[0]); pa[1] = __cosf(v0.y + th[1]);
        pa[2] = __cosf(v0.z + th[2]); pa[3] = __cosf(v0.w + th[3]);
        pa[4] = __cosf(v1.x + th[4]); pa[5] = __cosf(v1.y + th[5]);
        pa[6] = __cosf(v1.z + th[6]); pa[7] = __cosf(v1.w + th[7]);
        float4 u0 = *(const float4*)(xr + (lane + 32) * 8);
        float4 u1 = *(const float4*)(xr + (lane + 32) * 8 + 4);
        pb[0] = __cosf(u0.x + th[0]); pb[1] = __cosf(u0.y + th[1]);
        pb[2] = __cosf(u0.z + th[2]); pb[3] = __cosf(u0.w + th[3]);
        pb[4] = __cosf(u1.x + th[4]); pb[5] = __cosf(u1.y + th[5]);
        pb[6] = __cosf(u1.z + th[6]); pb[7] = __cosf(u1.w + th[7]);
    }

    float* Pw = &Psm[w][0][0];
    *(float4*)(Pw + lane * 8)            = make_float4(pa[0], pa[1], pa[2], pa[3]);
    *(float4*)(Pw + lane * 8 + 4)        = make_float4(pa[4], pa[5], pa[6], pa[7]);
    *(float4*)(Pw + (lane + 32) * 8)     = make_float4(pb[0], pb[1], pb[2], pb[3]);
    *(float4*)(Pw + (lane + 32) * 8 + 4) = make_float4(pb[4], pb[5], pb[6], pb[7]);
    __syncwarp();

    const float inv = 0.35355339059327373f;
    float qa[8], qb[8];
#pragma unroll
    for (int d = 0; d < 8; d++) { qa[d] = pa[d] * inv; qb[d] = pb[d] * inv; }

    float suma = 0.f, sumb = 0.f, oa[8], ob[8];
#pragma unroll
    for (int d = 0; d < 8; d++) { oa[d] = 0.f; ob[d] = 0.f; }

#pragma unroll 8
    for (int g = 0; g < NHEAD; g++) {
        float4 r0 = *(const float4*)(Pw + g * 8);
        float4 r1 = *(const float4*)(Pw + g * 8 + 4);
        float sa = qa[0]*r0.x + qa[1]*r0.y + qa[2]*r0.z + qa[3]*r0.w
                 + qa[4]*r1.x + qa[5]*r1.y + qa[6]*r1.z + qa[7]*r1.w;
        float sb = qb[0]*r0.x + qb[1]*r0.y + qb[2]*r0.z + qb[3]*r0.w
                 + qb[4]*r1.x + qb[5]*r1.y + qb[6]*r1.z + qb[7]*r1.w;
        float wa = __expf(sa), wb = __expf(sb);
        suma += wa; sumb += wb;
        oa[0] += wa*r0.x; oa[1] += wa*r0.y; oa[2] += wa*r0.z; oa[3] += wa*r0.w;
        oa[4] += wa*r1.x; oa[5] += wa*r1.y; oa[6] += wa*r1.z; oa[7] += wa*r1.w;
        ob[0] += wb*r0.x; ob[1] += wb*r0.y; ob[2] += wb*r0.z; ob[3] += wb*r0.w;
        ob[4] += wb*r1.x; ob[5] += wb*r1.y; ob[6] += wb*r1.z; ob[7] += wb*r1.w;
    }

    const float ra = 1.0f / suma, rb = 1.0f / sumb;
    const int b = token >> 11, s = token & 2047;
    const size_t idxA = ((size_t)b << 20) + ((size_t)lane << 14) + s * 8;
    const size_t idxB = ((size_t)b << 20) + ((size_t)(lane + 32) << 14) + s * 8;

    union { __nv_bfloat16 e[8]; uint4 v; } uh, ul;
#pragma unroll
    for (int d = 0; d < 8; d++) {
        float z = oa[d] * ra;
        uh.e[d] = __float2bfloat16(z);
        ul.e[d] = __float2bfloat16(z - __bfloat162float(uh.e[d]));
    }
    *(uint4*)(g_Zh + idxA) = uh.v;
    *(uint4*)(g_Zl + idxA) = ul.v;
#pragma unroll
    for (int d = 0; d < 8; d++) {
        float z = ob[d] * rb;
        uh.e[d] = __float2bfloat16(z);
        ul.e[d] = __float2bfloat16(z - __bfloat162float(uh.e[d]));
    }
    *(uint4*)(g_Zh + idxB) = uh.v;
    *(uint4*)(g_Zl + idxB) = ul.v;
}

// ---------------------------------------------------------------------------
// Kernel B: HMMA GEMM  Y[16384,512] = Z @ W^T + bias  (split-bf16, fp32 acc)
// CTA 128x128, 8 warps x (64x32), K chunks of 32, double-buffered cp.async.
// SMEM row stride 80B -> conflict-free ldmatrix (5r mod 8 permutation).
// ---------------------------------------------------------------------------
#define RSTRIDE 80
#define ARR     (128 * RSTRIDE)     // 10240 B per operand tile
#define O_ZH    0
#define O_ZL    (1 * ARR)
#define O_WH    (2 * ARR)
#define O_WL    (3 * ARR)
#define STAGE   (4 * ARR)           // 40960 B
#define SMEM_TOTAL (2 * STAGE)      // 81920 B

__global__ __launch_bounds__(256) void gemm_kernel(const float* __restrict__ bias,
                                                   float* __restrict__ Y) {
    extern __shared__ char smem[];
    const uint32_t smem_base = smem_to_u32(smem);
    const int tid = threadIdx.x, wid = tid >> 5, lane = tid & 31;
    const int bx = blockIdx.x, by = blockIdx.y;

    // cp.async slice: thread handles row=tid>>1, 32B half of each operand row
    const int row = tid >> 1, half = tid & 1;
    const size_t zbase = (size_t)(by * 128 + row) * EDIM + half * 16;
    const size_t wbase = (size_t)(bx * 128 + row) * EDIM + half * 16;
    const uint32_t sdst = smem_base + row * RSTRIDE + half * 32;

    // warp tile: wm in {0,1} (64 rows), wn in {0..3} (32 cols)
    const int wm = wid & 1, wn = wid >> 1;

    // ldmatrix lane addressing
    const int la_row = lane & 15;                       // A row in 16-tile
    const int la_kh  = (lane >> 4) & 1;                 // A 16B k-half
    const int lb_n   = (lane & 7) + ((lane & 16) >> 1); // B n in 16-group
    const int lb_kh  = (lane >> 3) & 1;                 // B 16B k-half

    float acc[4][4][4];
#pragma unroll
    for (int i = 0; i < 4; i++)
#pragma unroll
        for (int j = 0; j < 4; j++)
#pragma unroll
            for (int k = 0; k < 4; k++) acc[i][j][k] = 0.f;

#define ISSUE(c, st) do { \
    uint32_t d = sdst + (st) * STAGE; \
    size_t  zo = zbase + (size_t)(c) * 32; \
    size_t  wo = wbase + (size_t)(c) * 32; \
    CP16(d + O_ZH,      (const char*)(g_Zh + zo)); \
    CP16(d + O_ZH + 16, (const char*)(g_Zh + zo + 8)); \
    CP16(d + O_ZL,      (const char*)(g_Zl + zo)); \
    CP16(d + O_ZL + 16, (const char*)(g_Zl + zo + 8)); \
    CP16(d + O_WH,      (const char*)(g_Wh + wo)); \
    CP16(d + O_WH + 16, (const char*)(g_Wh + wo + 8)); \
    CP16(d + O_WL,      (const char*)(g_Wl + wo)); \
    CP16(d + O_WL + 16, (const char*)(g_Wl + wo + 8)); \
} while (0)

    ISSUE(0, 0);
    CP_COMMIT();

    for (int c = 0; c < EDIM / 32; c++) {
        const int st = c & 1;
        if (c + 1 < EDIM / 32) { ISSUE(c + 1, st ^ 1); CP_COMMIT(); CP_WAIT1(); }
        else                   { CP_WAIT0(); }
        __syncthreads();

        const uint32_t sg = smem_base + st * STAGE;
        // A lane base addresses (row part), per array
        const uint32_t aZH = sg + O_ZH + (wm * 64 + la_row) * RSTRIDE + la_kh * 16;
        const uint32_t aZL = sg + O_ZL + (wm * 64 + la_row) * RSTRIDE + la_kh * 16;
        const uint32_t bWH = sg + O_WH + (wn * 32 + lb_n) * RSTRIDE + lb_kh * 16;
        const uint32_t bWL = sg + O_WL + (wn * 32 + lb_n) * RSTRIDE + lb_kh * 16;

#pragma unroll
        for (int ks = 0; ks < 2; ks++) {
            const uint32_t ko = ks * 32;   // 16 bf16 = 32 bytes
            uint32_t ah[4][4], al[4][4], bh[4][2], bl[4][2];
#pragma unroll
            for (int mt = 0; mt < 4; mt++) {
                LDSM4(ah[mt], aZH + mt * 16 * RSTRIDE + ko);
                LDSM4(al[mt], aZL + mt * 16 * RSTRIDE + ko);
            }
#pragma unroll
            for (int np = 0; np < 2; np++) {
                uint32_t t[4];
                LDSM4(t, bWH + np * 16 * RSTRIDE + ko);
                bh[2*np][0] = t[0]; bh[2*np][1] = t[1];
                bh[2*np+1][0] = t[2]; bh[2*np+1][1] = t[3];
                LDSM4(t, bWL + np * 16 * RSTRIDE + ko);
                bl[2*np][0] = t[0]; bl[2*np][1] = t[1];
                bl[2*np+1][0] = t[2]; bl[2*np+1][1] = t[3];
            }
#pragma unroll
            for (int mt = 0; mt < 4; mt++)
#pragma unroll
                for (int nt = 0; nt < 4; nt++) {
                    MMA_BF16(acc[mt][nt], ah[mt], bh[nt]);
                    MMA_BF16(acc[mt][nt], al[mt], bh[nt]);
                    MMA_BF16(acc[mt][nt], ah[mt], bl[nt]);
                }
        }
        __syncthreads();
    }

    // Epilogue: fp32 accumulators + bias -> Y
    const int g = lane >> 2, cq = 2 * (lane & 3);
#pragma unroll
    for (int nt = 0; nt < 4; nt++) {
        const int col = bx * 128 + wn * 32 + nt * 8 + cq;
        const float2 bv = *(const float2*)(bias + col);
#pragma unroll
        for (int mt = 0; mt < 4; mt++) {
            const int r0 = by * 128 + wm * 64 + mt * 16 + g;
            float2 v0 = make_float2(acc[mt][nt][0] + bv.x, acc[mt][nt][1] + bv.y);
            float2 v1 = make_float2(acc[mt][nt][2] + bv.x, acc[mt][nt][3] + bv.y);
            *(float2*)(Y + (size_t)r0 * EDIM + col)       = v0;
            *(float2*)(Y + (size_t)(r0 + 8) * EDIM + col) = v1;
        }
    }
}

// ---------------------------------------------------------------------------
extern "C" void kernel_launch(void* const* d_in, const int* in_sizes, int n_in,
                              void* d_out, int out_size) {
    const float* x     = (const float*)d_in[0];
    const float* theta = (const float*)d_in[1];
    const float* W     = (const float*)d_in[2];
    const float* bias  = (const float*)d_in[3];
    float* out = (float*)d_out;

    cudaFuncSetAttribute(gemm_kernel, cudaFuncAttributeMaxDynamicSharedMemorySize, SMEM_TOTAL);

    wsplit_kernel<<<EDIM * EDIM / 256, 256>>>(W);
    qattn_kernel<<<NTOK / 8, 256>>>(x, theta);
    gemm_kernel<<<dim3(EDIM / 128, NTOK / 128), 256, SMEM_TOTAL>>>(bias, out);
}

// round 4
// speedup vs baseline: 1.8288x; 1.0920x over previous
#include <cuda_runtime.h>
#include <cuda_bf16.h>
#include <cstdint>

#define NTOK   (8 * 2048)
#define EDIM   512
#define NHEAD  64
#define DK     8

typedef unsigned long long u64;

// Split-bf16 operands (hi + lo together carry ~17 mantissa bits of fp32)
__device__ __nv_bfloat16 g_Zh[NTOK * EDIM];
__device__ __nv_bfloat16 g_Zl[NTOK * EDIM];
__device__ __nv_bfloat16 g_Wh[EDIM * EDIM];
__device__ __nv_bfloat16 g_Wl[EDIM * EDIM];

__device__ __forceinline__ uint32_t smem_to_u32(const void* p) {
    uint32_t a;
    asm("{ .reg .u64 t; cvta.to.shared.u64 t, %1; cvt.u32.u64 %0, t; }" : "=r"(a) : "l"(p));
    return a;
}

// Packed fp32x2 math (Blackwell)
__device__ __forceinline__ void fma2(u64 &d, u64 a, u64 b) {
    asm("fma.rn.f32x2 %0, %1, %2, %3;" : "=l"(d) : "l"(a), "l"(b), "l"(d));
}
__device__ __forceinline__ void add2(u64 &d, u64 a) {
    asm("add.rn.f32x2 %0, %1, %2;" : "=l"(d) : "l"(d), "l"(a));
}
__device__ __forceinline__ u64 pack2(float lo, float hi) {
    u64 r; asm("mov.b64 %0, {%1, %2};" : "=l"(r) : "f"(lo), "f"(hi)); return r;
}
__device__ __forceinline__ float2 unpack2(u64 v) {
    float2 r; asm("mov.b64 {%0, %1}, %2;" : "=f"(r.x), "=f"(r.y) : "l"(v)); return r;
}

// Baseline-PTX tensor path (sm_80+: cp.async, ldmatrix, bf16 mma.sync)
#define CP16(dst, src) \
    asm volatile("cp.async.cg.shared.global [%0], [%1], 16;" :: "r"(dst), "l"(src))
#define CP_COMMIT()  asm volatile("cp.async.commit_group;" ::: "memory")
#define CP_WAIT1()   asm volatile("cp.async.wait_group 1;" ::: "memory")
#define CP_WAIT0()   asm volatile("cp.async.wait_group 0;" ::: "memory")

#define LDSM4(r, addr) \
    asm volatile("ldmatrix.sync.aligned.m8n8.x4.shared.b16 {%0,%1,%2,%3}, [%4];" \
        : "=r"((r)[0]), "=r"((r)[1]), "=r"((r)[2]), "=r"((r)[3]) : "r"(addr))

#define MMA_BF16(d, a, b) \
    asm volatile("mma.sync.aligned.m16n8k16.row.col.f32.bf16.bf16.f32 " \
        "{%0,%1,%2,%3}, {%4,%5,%6,%7}, {%8,%9}, {%0,%1,%2,%3};" \
        : "+f"((d)[0]), "+f"((d)[1]), "+f"((d)[2]), "+f"((d)[3]) \
        : "r"((a)[0]), "r"((a)[1]), "r"((a)[2]), "r"((a)[3]), "r"((b)[0]), "r"((b)[1]))

// ---------------------------------------------------------------------------
// Kernel A: blocks [0, NTOK/8): projection + head-axis attention (warp/token).
//           blocks [NTOK/8, +EDIM*EDIM/256): W hi/lo split (merged launch).
// Bounded scores (|s| <= 2.83) -> streaming softmax, base-2 exponent domain.
// ---------------------------------------------------------------------------
#define QBLOCKS (NTOK / 8)

__global__ __launch_bounds__(256) void qattn_kernel(const float* __restrict__ x,
                                                    const float* __restrict__ theta,
                                                    const float* __restrict__ W) {
    const int tid = threadIdx.x;

    if (blockIdx.x >= QBLOCKS) {   // -------- W split branch --------
        int i = (blockIdx.x - QBLOCKS) * 256 + tid;
        float w = W[i];
        __nv_bfloat16 h = __float2bfloat16(w);
        g_Wh[i] = h;
        g_Wl[i] = __float2bfloat16(w - __bfloat162float(h));
        return;
    }

    __shared__ float Psm[8][NHEAD][DK];
    __shared__ float th[DK];
    if (tid < DK) th[tid] = theta[tid];
    __syncthreads();

    const int w = tid >> 5, lane = tid & 31;
    const int token = blockIdx.x * 8 + w;
    const float* xr = x + (size_t)token * EDIM;

    float pa[8], pb[8];
    {
        float4 v0 = *(const float4*)(xr + lane * 8);
        float4 v1 = *(const float4*)(xr + lane * 8 + 4);
        pa[0] = __cosf(v0.x + th[0]); pa[1] = __cosf(v0.y + th[1]);
        pa[2] = __cosf(v0.z + th[2]); pa[3] = __cosf(v0.w + th[3]);
        pa[4] = __cosf(v1.x + th[4]); pa[5] = __cosf(v1.y + th[5]);
        pa[6] = __cosf(v1.z + th[6]); pa[7] = __cosf(v1.w + th[7]);
        float4 u0 = *(const float4*)(xr + (lane + 32) * 8);
        float4 u1 = *(const float4*)(xr + (lane + 32) * 8 + 4);
        pb[0] = __cosf(u0.x + th[0]); pb[1] = __cosf(u0.y + th[1]);
        pb[2] = __cosf(u0.z + th[2]); pb[3] = __cosf(u0.w + th[3]);
        pb[4] = __cosf(u1.x + th[4]); pb[5] = __cosf(u1.y + th[5]);
        pb[6] = __cosf(u1.z + th[6]); pb[7] = __cosf(u1.w + th[7]);
    }

    float* Pw = &Psm[w][0][0];
    *(float4*)(Pw + lane * 8)            = make_float4(pa[0], pa[1], pa[2], pa[3]);
    *(float4*)(Pw + lane * 8 + 4)        = make_float4(pa[4], pa[5], pa[6], pa[7]);
    *(float4*)(Pw + (lane + 32) * 8)     = make_float4(pb[0], pb[1], pb[2], pb[3]);
    *(float4*)(Pw + (lane + 32) * 8 + 4) = make_float4(pb[4], pb[5], pb[6], pb[7]);
    __syncwarp();

    // scale = 1/sqrt(8) * 1/ln(2): softmax_e(s) == softmax_2(s/ln2)
    const float inv = 0.35355339059327373f * 1.4426950408889634f;
    u64 uqa[4], uqb[4];
#pragma unroll
    for (int i = 0; i < 4; i++) {
        uqa[i] = pack2(pa[2*i] * inv, pa[2*i+1] * inv);
        uqb[i] = pack2(pb[2*i] * inv, pb[2*i+1] * inv);
    }

    u64 sum2 = 0ull;                 // (suma, sumb)
    u64 uoa[4], uob[4];
#pragma unroll
    for (int i = 0; i < 4; i++) { uoa[i] = 0ull; uob[i] = 0ull; }

    const ulonglong2* Pw2 = (const ulonglong2*)Pw;
#pragma unroll 8
    for (int g = 0; g < NHEAD; g++) {
        ulonglong2 p0 = Pw2[g * 2];       // pairs (k0,k1),(k2,k3)
        ulonglong2 p1 = Pw2[g * 2 + 1];   // pairs (k4,k5),(k6,k7)
        u64 ta = 0ull, tb = 0ull;
        fma2(ta, uqa[0], p0.x); fma2(ta, uqa[1], p0.y);
        fma2(ta, uqa[2], p1.x); fma2(ta, uqa[3], p1.y);
        fma2(tb, uqb[0], p0.x); fma2(tb, uqb[1], p0.y);
        fma2(tb, uqb[2], p1.x); fma2(tb, uqb[3], p1.y);
        float2 va = unpack2(ta), vb = unpack2(tb);
        float wa = exp2f(va.x + va.y);
        float wb = exp2f(vb.x + vb.y);
        add2(sum2, pack2(wa, wb));
        u64 waa = pack2(wa, wa), wbb = pack2(wb, wb);
        fma2(uoa[0], p0.x, waa); fma2(uoa[1], p0.y, waa);
        fma2(uoa[2], p1.x, waa); fma2(uoa[3], p1.y, waa);
        fma2(uob[0], p0.x, wbb); fma2(uob[1], p0.y, wbb);
        fma2(uob[2], p1.x, wbb); fma2(uob[3], p1.y, wbb);
    }

    float2 sums = unpack2(sum2);
    const float ra = 1.0f / sums.x, rb = 1.0f / sums.y;
    const int b = token >> 11, s = token & 2047;
    const size_t idxA = ((size_t)b << 20) + ((size_t)lane << 14) + s * 8;
    const size_t idxB = ((size_t)b << 20) + ((size_t)(lane + 32) << 14) + s * 8;

    union { __nv_bfloat16 e[8]; uint4 v; } uh, ul;
#pragma unroll
    for (int i = 0; i < 4; i++) {
        float2 v = unpack2(uoa[i]);
        float z0 = v.x * ra, z1 = v.y * ra;
        uh.e[2*i]   = __float2bfloat16(z0);
        ul.e[2*i]   = __float2bfloat16(z0 - __bfloat162float(uh.e[2*i]));
        uh.e[2*i+1] = __float2bfloat16(z1);
        ul.e[2*i+1] = __float2bfloat16(z1 - __bfloat162float(uh.e[2*i+1]));
    }
    *(uint4*)(g_Zh + idxA) = uh.v;
    *(uint4*)(g_Zl + idxA) = ul.v;
#pragma unroll
    for (int i = 0; i < 4; i++) {
        float2 v = unpack2(uob[i]);
        float z0 = v.x * rb, z1 = v.y * rb;
        uh.e[2*i]   = __float2bfloat16(z0);
        ul.e[2*i]   = __float2bfloat16(z0 - __bfloat162float(uh.e[2*i]));
        uh.e[2*i+1] = __float2bfloat16(z1);
        ul.e[2*i+1] = __float2bfloat16(z1 - __bfloat162float(uh.e[2*i+1]));
    }
    *(uint4*)(g_Zh + idxB) = uh.v;
    *(uint4*)(g_Zl + idxB) = ul.v;
}

// ---------------------------------------------------------------------------
// Kernel B: HMMA GEMM  Y[16384,512] = Z @ W^T + bias  (split-bf16, fp32 acc)
// CTA 128x128, 8 warps x (64x32), K chunks of 32, double-buffered cp.async.
// SMEM row stride 80B -> conflict-free ldmatrix. Target 2 CTAs/SM.
// ---------------------------------------------------------------------------
#define RSTRIDE 80
#define ARR     (128 * RSTRIDE)
#define O_ZH    0
#define O_ZL    (1 * ARR)
#define O_WH    (2 * ARR)
#define O_WL    (3 * ARR)
#define STAGE   (4 * ARR)           // 40960 B
#define SMEM_TOTAL (2 * STAGE)      // 81920 B

__global__ __launch_bounds__(256, 2) void gemm_kernel(const float* __restrict__ bias,
                                                      float* __restrict__ Y) {
    extern __shared__ char smem[];
    const uint32_t smem_base = smem_to_u32(smem);
    const int tid = threadIdx.x, wid = tid >> 5, lane = tid & 31;
    const int bx = blockIdx.x, by = blockIdx.y;

    const int row = tid >> 1, half = tid & 1;
    const size_t zbase = (size_t)(by * 128 + row) * EDIM + half * 16;
    const size_t wbase = (size_t)(bx * 128 + row) * EDIM + half * 16;
    const uint32_t sdst = smem_base + row * RSTRIDE + half * 32;

    const int wm = wid & 1, wn = wid >> 1;

    const int la_row = lane & 15;
    const int la_kh  = (lane >> 4) & 1;
    const int lb_n   = (lane & 7) + ((lane & 16) >> 1);
    const int lb_kh  = (lane >> 3) & 1;

    float acc[4][4][4];
#pragma unroll
    for (int i = 0; i < 4; i++)
#pragma unroll
        for (int j = 0; j < 4; j++)
#pragma unroll
            for (int k = 0; k < 4; k++) acc[i][j][k] = 0.f;

#define ISSUE(c, st) do { \
    uint32_t d = sdst + (st) * STAGE; \
    size_t  zo = zbase + (size_t)(c) * 32; \
    size_t  wo = wbase + (size_t)(c) * 32; \
    CP16(d + O_ZH,      (const char*)(g_Zh + zo)); \
    CP16(d + O_ZH + 16, (const char*)(g_Zh + zo + 8)); \
    CP16(d + O_ZL,      (const char*)(g_Zl + zo)); \
    CP16(d + O_ZL + 16, (const char*)(g_Zl + zo + 8)); \
    CP16(d + O_WH,      (const char*)(g_Wh + wo)); \
    CP16(d + O_WH + 16, (const char*)(g_Wh + wo + 8)); \
    CP16(d + O_WL,      (const char*)(g_Wl + wo)); \
    CP16(d + O_WL + 16, (const char*)(g_Wl + wo + 8)); \
} while (0)

    ISSUE(0, 0);
    CP_COMMIT();

    for (int c = 0; c < EDIM / 32; c++) {
        const int st = c & 1;
        if (c + 1 < EDIM / 32) { ISSUE(c + 1, st ^ 1); CP_COMMIT(); CP_WAIT1(); }
        else                   { CP_WAIT0(); }
        __syncthreads();

        const uint32_t sg = smem_base + st * STAGE;
        const uint32_t aZH = sg + O_ZH + (wm * 64 + la_row) * RSTRIDE + la_kh * 16;
        const uint32_t aZL = sg + O_ZL + (wm * 64 + la_row) * RSTRIDE + la_kh * 16;
        const uint32_t bWH = sg + O_WH + (wn * 32 + lb_n) * RSTRIDE + lb_kh * 16;
        const uint32_t bWL = sg + O_WL + (wn * 32 + lb_n) * RSTRIDE + lb_kh * 16;

#pragma unroll
        for (int ks = 0; ks < 2; ks++) {
            const uint32_t ko = ks * 32;
            uint32_t bh[4][2], bl[4][2];
#pragma unroll
            for (int np = 0; np < 2; np++) {
                uint32_t t[4];
                LDSM4(t, bWH + np * 16 * RSTRIDE + ko);
                bh[2*np][0] = t[0]; bh[2*np][1] = t[1];
                bh[2*np+1][0] = t[2]; bh[2*np+1][1] = t[3];
                LDSM4(t, bWL + np * 16 * RSTRIDE + ko);
                bl[2*np][0] = t[0]; bl[2*np][1] = t[1];
                bl[2*np+1][0] = t[2]; bl[2*np+1][1] = t[3];
            }
#pragma unroll
            for (int mt = 0; mt < 4; mt++) {
                uint32_t ah[4], al[4];
                LDSM4(ah, aZH + mt * 16 * RSTRIDE + ko);
                LDSM4(al, aZL + mt * 16 * RSTRIDE + ko);
#pragma unroll
                for (int nt = 0; nt < 4; nt++) {
                    MMA_BF16(acc[mt][nt], ah, bh[nt]);
                    MMA_BF16(acc[mt][nt], al, bh[nt]);
                    MMA_BF16(acc[mt][nt], ah, bl[nt]);
                }
            }
        }
        __syncthreads();
    }

    const int g = lane >> 2, cq = 2 * (lane & 3);
#pragma unroll
    for (int nt = 0; nt < 4; nt++) {
        const int col = bx * 128 + wn * 32 + nt * 8 + cq;
        const float2 bv = *(const float2*)(bias + col);
#pragma unroll
        for (int mt = 0; mt < 4; mt++) {
            const int r0 = by * 128 + wm * 64 + mt * 16 + g;
            float2 v0 = make_float2(acc[mt][nt][0] + bv.x, acc[mt][nt][1] + bv.y);
            float2 v1 = make_float2(acc[mt][nt][2] + bv.x, acc[mt][nt][3] + bv.y);
            *(float2*)(Y + (size_t)r0 * EDIM + col)       = v0;
            *(float2*)(Y + (size_t)(r0 + 8) * EDIM + col) = v1;
        }
    }
}

// ---------------------------------------------------------------------------
extern "C" void kernel_launch(void* const* d_in, const int* in_sizes, int n_in,
                              void* d_out, int out_size) {
    const float* x     = (const float*)d_in[0];
    const float* theta = (const float*)d_in[1];
    const float* W     = (const float*)d_in[2];
    const float* bias  = (const float*)d_in[3];
    float* out = (float*)d_out;

    cudaFuncSetAttribute(gemm_kernel, cudaFuncAttributeMaxDynamicSharedMemorySize, SMEM_TOTAL);

    qattn_kernel<<<QBLOCKS + EDIM * EDIM / 256, 256>>>(x, theta, W);
    gemm_kernel<<<dim3(EDIM / 128, NTOK / 128), 256, SMEM_TOTAL>>>(bias, out);
}